// round 2
// baseline (speedup 1.0000x reference)
#include <cuda_runtime.h>

#define T_LEN  32768
#define NROWS  1024
#define NT     1024
#define IT     8                    // items per thread per chunk
#define CHUNK  (NT * IT)            // 8192 floats per chunk
#define NCHUNK (T_LEN / CHUNK)      // 4 chunks

__device__ float g_partial[NROWS];
__device__ unsigned int g_count;

__global__ void __launch_bounds__(NT, 1)
wass_kernel(const float* __restrict__ yp, const float* __restrict__ yt,
            float* __restrict__ out) {
    // ping-pong scan scratch: [33] per parity ([0..31] warp values, [32] chunk total)
    __shared__ float scan_scr[2][33];
    __shared__ double dscr[32];
    __shared__ bool is_last;

    const int tid  = threadIdx.x;
    const int lane = tid & 31;
    const int wid  = tid >> 5;

    const long rowbase = (long)blockIdx.x * T_LEN;
    const float4* __restrict__ p4 = (const float4*)(yp + rowbase);
    const float4* __restrict__ t4 = (const float4*)(yt + rowbase);

    // Prefetch chunk 0 into registers (2 float4 per tensor per thread).
    float4 pa0, pa1, ta0, ta1;
    {
        int v = tid * 2;
        pa0 = p4[v];     pa1 = p4[v + 1];
        ta0 = t4[v];     ta1 = t4[v + 1];
    }

    float carry_total = 0.0f;   // row cumsum total over completed chunks
    float acc = 0.0f;

    #pragma unroll
    for (int c = 0; c < NCHUNK; c++) {
        // Consume prefetched regs -> diff segment (8 contiguous elements).
        float d[IT];
        d[0] = pa0.x - ta0.x;  d[1] = pa0.y - ta0.y;
        d[2] = pa0.z - ta0.z;  d[3] = pa0.w - ta0.w;
        d[4] = pa1.x - ta1.x;  d[5] = pa1.y - ta1.y;
        d[6] = pa1.z - ta1.z;  d[7] = pa1.w - ta1.w;

        // Issue next chunk's loads NOW (overlap with scan below).
        if (c + 1 < NCHUNK) {
            int v = (c + 1) * (CHUNK / 4) + tid * 2;
            pa0 = p4[v];     pa1 = p4[v + 1];
            ta0 = t4[v];     ta1 = t4[v + 1];
        }

        // Per-thread segment sum (tree).
        float seg = ((d[0] + d[1]) + (d[2] + d[3]))
                  + ((d[4] + d[5]) + (d[6] + d[7]));

        // Warp inclusive scan of segment sums.
        float inc = seg;
        #pragma unroll
        for (int o = 1; o < 32; o <<= 1) {
            float y = __shfl_up_sync(0xffffffffu, inc, o);
            if (lane >= o) inc += y;
        }

        float* scr = scan_scr[c & 1];
        if (lane == 31) scr[wid] = inc;
        __syncthreads();
        if (wid == 0) {
            float wv = scr[lane];
            float winc = wv;
            #pragma unroll
            for (int o = 1; o < 32; o <<= 1) {
                float y = __shfl_up_sync(0xffffffffu, winc, o);
                if (lane >= o) winc += y;
            }
            scr[lane] = winc - wv;                  // exclusive warp prefix
            if (lane == 31) scr[32] = winc;         // chunk total
        }
        __syncthreads();

        // Exclusive prefix for this thread's segment start.
        float run = carry_total + scr[wid] + (inc - seg);
        carry_total += scr[32];

        // Weighted |cumsum| accumulation over the segment.
        const int idx0 = c * CHUNK + tid * IT;
        #pragma unroll
        for (int k = 0; k < IT; k++) {
            run += d[k];
            float w = (float)(T_LEN - (idx0 + k));  // weight T - t
            acc = fmaf(fabsf(run), w, acc);
        }
        // No extra sync needed: next iteration uses the other scr buffer.
    }

    // Deterministic block reduction of acc.
    #pragma unroll
    for (int o = 16; o > 0; o >>= 1) acc += __shfl_down_sync(0xffffffffu, acc, o);
    __syncthreads();
    if (lane == 0) scan_scr[0][wid] = acc;
    __syncthreads();
    if (wid == 0) {
        float v = scan_scr[0][lane];
        #pragma unroll
        for (int o = 16; o > 0; o >>= 1) v += __shfl_down_sync(0xffffffffu, v, o);
        if (lane == 0) {
            g_partial[blockIdx.x] = v;
            __threadfence();
            unsigned int prev = atomicAdd(&g_count, 1u);
            is_last = (prev == (unsigned int)(gridDim.x - 1));
        }
    }
    __syncthreads();

    // Last block: deterministic final reduce of all 1024 partials.
    if (is_last) {
        if (tid == 0) g_count = 0;       // reset for graph replay
        double v = (double)g_partial[tid];
        #pragma unroll
        for (int o = 16; o > 0; o >>= 1) v += __shfl_down_sync(0xffffffffu, v, o);
        if (lane == 0) dscr[wid] = v;
        __syncthreads();
        if (wid == 0) {
            double x = dscr[lane];
            #pragma unroll
            for (int o = 16; o > 0; o >>= 1) x += __shfl_down_sync(0xffffffffu, x, o);
            if (lane == 0) {
                double tc = (double)T_LEN * 16.0;            // T*C
                double scale = 2.0 / (tc * (tc + 1.0));
                out[0] = (float)((x / 64.0) * scale);        // mean over B=64
            }
        }
    }
}

extern "C" void kernel_launch(void* const* d_in, const int* in_sizes, int n_in,
                              void* d_out, int out_size) {
    (void)in_sizes; (void)n_in; (void)out_size;
    const float* y_pred = (const float*)d_in[0];
    const float* y_true = (const float*)d_in[1];
    float* out = (float*)d_out;
    wass_kernel<<<NROWS, NT>>>(y_pred, y_true, out);
}

// round 3
// speedup vs baseline: 1.0804x; 1.0804x over previous
#include <cuda_runtime.h>

#define T_LEN  32768
#define NROWS  1024
#define NT     1024
#define IT     8                    // items per thread per chunk
#define CHUNK  (NT * IT)            // 8192 floats per chunk
#define CPR    (T_LEN / CHUNK)      // 4 chunks per row
#define GRID   128
#define RPB    (NROWS / GRID)       // 8 rows per block
#define FLAT   (RPB * CPR)          // 32 flat chunks per block

__device__ double g_partial[GRID];
__device__ unsigned int g_count;

__global__ void __launch_bounds__(NT, 1)
wass_kernel(const float* __restrict__ yp, const float* __restrict__ yt,
            float* __restrict__ out) {
    __shared__ float scan_scr[2][33];   // ping-pong: [0..31] warp prefixes, [32] chunk total
    __shared__ double dscr[32];
    __shared__ bool is_last;

    const int tid  = threadIdx.x;
    const int lane = tid & 31;
    const int wid  = tid >> 5;
    const long blockrow0 = (long)blockIdx.x * RPB;

    // Prefetch flat chunk 0.
    float4 pa0, pa1, ta0, ta1;
    {
        const float4* p4 = (const float4*)(yp + blockrow0 * T_LEN);
        const float4* t4 = (const float4*)(yt + blockrow0 * T_LEN);
        int v = tid * 2;
        pa0 = p4[v]; pa1 = p4[v + 1];
        ta0 = t4[v]; ta1 = t4[v + 1];
    }

    double dacc = 0.0;          // per-thread, across rows (promoted per row)
    float  acc  = 0.0f;         // per-row weighted accumulator
    float  carry_total = 0.0f;  // row cumsum carry

    #pragma unroll 4
    for (int f = 0; f < FLAT; f++) {
        const int cir = f & (CPR - 1);          // chunk index within row

        // Consume prefetched regs.
        float d[IT];
        d[0] = pa0.x - ta0.x;  d[1] = pa0.y - ta0.y;
        d[2] = pa0.z - ta0.z;  d[3] = pa0.w - ta0.w;
        d[4] = pa1.x - ta1.x;  d[5] = pa1.y - ta1.y;
        d[6] = pa1.z - ta1.z;  d[7] = pa1.w - ta1.w;

        // Prefetch flat chunk f+1 (crosses row boundaries — keeps DRAM busy).
        if (f + 1 < FLAT) {
            const int nf   = f + 1;
            const long nrow = blockrow0 + (nf >> 2);
            const int  ncir = nf & (CPR - 1);
            const float4* p4 = (const float4*)(yp + nrow * T_LEN);
            const float4* t4 = (const float4*)(yt + nrow * T_LEN);
            int v = ncir * (CHUNK / 4) + tid * 2;
            pa0 = p4[v]; pa1 = p4[v + 1];
            ta0 = t4[v]; ta1 = t4[v + 1];
        }

        // Per-thread segment sum.
        float seg = ((d[0] + d[1]) + (d[2] + d[3]))
                  + ((d[4] + d[5]) + (d[6] + d[7]));

        // Warp inclusive scan.
        float inc = seg;
        #pragma unroll
        for (int o = 1; o < 32; o <<= 1) {
            float y = __shfl_up_sync(0xffffffffu, inc, o);
            if (lane >= o) inc += y;
        }

        float* scr = scan_scr[f & 1];
        if (lane == 31) scr[wid] = inc;
        __syncthreads();
        if (wid == 0) {
            float wv = scr[lane];
            float winc = wv;
            #pragma unroll
            for (int o = 1; o < 32; o <<= 1) {
                float y = __shfl_up_sync(0xffffffffu, winc, o);
                if (lane >= o) winc += y;
            }
            scr[lane] = winc - wv;              // exclusive warp prefix
            if (lane == 31) scr[32] = winc;     // chunk total
        }
        __syncthreads();

        float run = carry_total + scr[wid] + (inc - seg);
        carry_total += scr[32];

        // Weighted |cumsum| accumulation.
        const int idx0 = cir * CHUNK + tid * IT;
        #pragma unroll
        for (int k = 0; k < IT; k++) {
            run += d[k];
            float w = (float)(T_LEN - (idx0 + k));
            acc = fmaf(fabsf(run), w, acc);
        }

        // Row boundary: fold into double, reset row state.
        if (cir == CPR - 1) {
            dacc += (double)acc;
            acc = 0.0f;
            carry_total = 0.0f;
        }
    }

    // Deterministic block reduction of dacc.
    #pragma unroll
    for (int o = 16; o > 0; o >>= 1)
        dacc += __shfl_down_sync(0xffffffffu, dacc, o);
    if (lane == 0) dscr[wid] = dacc;
    __syncthreads();
    if (wid == 0) {
        double v = dscr[lane];
        #pragma unroll
        for (int o = 16; o > 0; o >>= 1)
            v += __shfl_down_sync(0xffffffffu, v, o);
        if (lane == 0) {
            g_partial[blockIdx.x] = v;
            __threadfence();
            unsigned int prev = atomicAdd(&g_count, 1u);
            is_last = (prev == (unsigned int)(gridDim.x - 1));
        }
    }
    __syncthreads();

    // Last block: final reduce of 128 partials (warp 0..3 -> warp 0).
    if (is_last) {
        if (tid == 0) g_count = 0;   // reset for graph replay
        if (tid < GRID) {
            double v = g_partial[tid];
            #pragma unroll
            for (int o = 16; o > 0; o >>= 1)
                v += __shfl_down_sync(0xffffffffu, v, o);
            if (lane == 0) dscr[wid] = v;
        }
        __syncthreads();
        if (tid == 0) {
            double x = dscr[0] + dscr[1] + dscr[2] + dscr[3];
            double tc = (double)T_LEN * 16.0;           // T*C
            double scale = 2.0 / (tc * (tc + 1.0));
            out[0] = (float)((x / 64.0) * scale);       // mean over B=64
        }
    }
}

extern "C" void kernel_launch(void* const* d_in, const int* in_sizes, int n_in,
                              void* d_out, int out_size) {
    (void)in_sizes; (void)n_in; (void)out_size;
    const float* y_pred = (const float*)d_in[0];
    const float* y_true = (const float*)d_in[1];
    float* out = (float*)d_out;
    wass_kernel<<<GRID, NT>>>(y_pred, y_true, out);
}